// round 1
// baseline (speedup 1.0000x reference)
#include <cuda_runtime.h>

#define BB 4
#define NN 10000
#define CC 128
#define KK 16
#define OC 128
#define C2 256        // 2*C
#define TILE 32       // nodes per CTA
#define NTHREADS 256  // 8 warps, warp w owns nodes 4w..4w+3

// De-interleaved, transposed weights: g_Wt[c2][o]
//   c2 in [0,128)   -> W[o][2*c2]     (weights hitting self feature x)
//   c2 in [128,256) -> W[o][2*(c2-128)+1] (weights hitting rel feature)
__device__ float g_Wt[C2 * OC];

__global__ void transpose_W_kernel(const float* __restrict__ W) {
    int idx = blockIdx.x * blockDim.x + threadIdx.x;
    if (idx < C2 * OC) {
        int c2p = idx >> 7;   // 0..255
        int o   = idx & 127;  // 0..127
        int src_c = (c2p < CC) ? (2 * c2p) : (2 * (c2p - CC) + 1);
        g_Wt[idx] = W[o * C2 + src_c];
    }
}

__global__ void __launch_bounds__(NTHREADS)
mrconv_kernel(const float* __restrict__ x,
              const int*   __restrict__ edge,
              const float* __restrict__ bias,
              float*       __restrict__ out) {
    // feat_s[node][c2p]: [0,128) = x(self), [128,256) = rel (max_k xj-xi)
    __shared__ float feat_s[TILE][C2];

    const int b     = blockIdx.y;
    const int tile0 = blockIdx.x * TILE;
    const int warp  = threadIdx.x >> 5;
    const int lane  = threadIdx.x & 31;

    const float* __restrict__ xb = x + (size_t)b * NN * CC;

    // ---------------- Phase 1: gather + max-relative, 4 nodes per warp ----
    #pragma unroll
    for (int i = 0; i < 4; ++i) {
        const int nl = warp * 4 + i;
        const int n  = tile0 + nl;
        if (n >= NN) {
            ((float4*)feat_s[nl])[lane]      = make_float4(0.f, 0.f, 0.f, 0.f);
            ((float4*)feat_s[nl])[32 + lane] = make_float4(0.f, 0.f, 0.f, 0.f);
            continue;
        }
        // lanes 0..15 load edge[0] (j = source), lanes 16..31 load edge[1] (i = self idx)
        const int s = lane >> 4;
        const int k = lane & 15;
        const int idx = __ldg(&edge[(((size_t)s * BB + b) * NN + n) * KK + k]);

        const float4 xs = __ldg((const float4*)(xb + (size_t)n * CC) + lane);

        float4 rel = make_float4(-3.402823466e38f, -3.402823466e38f,
                                 -3.402823466e38f, -3.402823466e38f);
        #pragma unroll 4
        for (int kk = 0; kk < KK; ++kk) {
            const int jn = __shfl_sync(0xffffffffu, idx, kk);        // edge[0]
            const int im = __shfl_sync(0xffffffffu, idx, kk + 16);   // edge[1]
            const float4 vj = __ldg((const float4*)(xb + (size_t)jn * CC) + lane);
            const float4 vi = __ldg((const float4*)(xb + (size_t)im * CC) + lane);
            rel.x = fmaxf(rel.x, vj.x - vi.x);
            rel.y = fmaxf(rel.y, vj.y - vi.y);
            rel.z = fmaxf(rel.z, vj.z - vi.z);
            rel.w = fmaxf(rel.w, vj.w - vi.w);
        }
        ((float4*)feat_s[nl])[lane]      = xs;   // channels 4*lane..4*lane+3
        ((float4*)feat_s[nl])[32 + lane] = rel;  // 128 + 4*lane ..
    }
    __syncwarp();  // warp reads only its own feat rows -> no block sync needed

    // ---------------- Phase 2: per-warp GEMM 4 nodes x 128 outs -----------
    float acc[4][4];
    #pragma unroll
    for (int i = 0; i < 4; ++i)
        #pragma unroll
        for (int j = 0; j < 4; ++j) acc[i][j] = 0.f;

    const float4* __restrict__ Wt4 = (const float4*)g_Wt;
    const int n0 = warp * 4;

    #pragma unroll 4
    for (int c2 = 0; c2 < C2; ++c2) {
        const float4 wv = __ldg(&Wt4[c2 * 32 + lane]);  // Wt[c2][4*lane..+3], L1-hot
        const float f0 = feat_s[n0 + 0][c2];            // warp-broadcast LDS
        const float f1 = feat_s[n0 + 1][c2];
        const float f2 = feat_s[n0 + 2][c2];
        const float f3 = feat_s[n0 + 3][c2];
        acc[0][0] += f0 * wv.x; acc[0][1] += f0 * wv.y; acc[0][2] += f0 * wv.z; acc[0][3] += f0 * wv.w;
        acc[1][0] += f1 * wv.x; acc[1][1] += f1 * wv.y; acc[1][2] += f1 * wv.z; acc[1][3] += f1 * wv.w;
        acc[2][0] += f2 * wv.x; acc[2][1] += f2 * wv.y; acc[2][2] += f2 * wv.z; acc[2][3] += f2 * wv.w;
        acc[3][0] += f3 * wv.x; acc[3][1] += f3 * wv.y; acc[3][2] += f3 * wv.z; acc[3][3] += f3 * wv.w;
    }

    const float4 bv = __ldg((const float4*)bias + lane);
    #pragma unroll
    for (int i = 0; i < 4; ++i) {
        const int n = tile0 + n0 + i;
        if (n < NN) {
            float4 o4;
            o4.x = fmaxf(acc[i][0] + bv.x, 0.f);
            o4.y = fmaxf(acc[i][1] + bv.y, 0.f);
            o4.z = fmaxf(acc[i][2] + bv.z, 0.f);
            o4.w = fmaxf(acc[i][3] + bv.w, 0.f);
            ((float4*)(out + ((size_t)b * NN + n) * OC))[lane] = o4;
        }
    }
}

extern "C" void kernel_launch(void* const* d_in, const int* in_sizes, int n_in,
                              void* d_out, int out_size) {
    const float* x    = (const float*)d_in[0];  // [4,10000,128] f32
    const int*   edge = (const int*)  d_in[1];  // [2,4,10000,16] i32
    const float* W    = (const float*)d_in[2];  // [128,256] f32
    const float* bias = (const float*)d_in[3];  // [128] f32
    float* out = (float*)d_out;                 // [4,10000,128] f32

    transpose_W_kernel<<<(C2 * OC + 255) / 256, 256>>>(W);

    dim3 grid((NN + TILE - 1) / TILE, BB);
    mrconv_kernel<<<grid, NTHREADS>>>(x, edge, bias, out);
}

// round 2
// speedup vs baseline: 1.1986x; 1.1986x over previous
#include <cuda_runtime.h>

#define BB 4
#define NN 10000
#define CC 128
#define KK 16
#define OC 128
#define C2 256        // 2*C
#define TILE 64       // nodes per CTA
#define NPW 8         // nodes per warp
#define NTHREADS 256  // 8 warps

// De-interleaved, transposed weights: g_Wt[c2][o]
//   c2 in [0,128)   -> W[o][2*c2]          (weights hitting self feature x)
//   c2 in [128,256) -> W[o][2*(c2-128)+1]  (weights hitting rel feature)
__device__ float g_Wt[C2 * OC];

__global__ void transpose_W_kernel(const float* __restrict__ W) {
    int idx = blockIdx.x * blockDim.x + threadIdx.x;
    if (idx < C2 * OC) {
        int c2p = idx >> 7;   // 0..255
        int o   = idx & 127;  // 0..127
        int src_c = (c2p < CC) ? (2 * c2p) : (2 * (c2p - CC) + 1);
        g_Wt[idx] = W[o * C2 + src_c];
    }
}

__global__ void __launch_bounds__(NTHREADS)
mrconv_kernel(const float* __restrict__ x,
              const int*   __restrict__ edge,
              const float* __restrict__ bias,
              float*       __restrict__ out) {
    // feat_s[node][c2p]: [0,128) = x(self), [128,256) = rel (max_k xj-xi)
    __shared__ float feat_s[TILE][C2];

    const int b     = blockIdx.y;
    const int tile0 = blockIdx.x * TILE;
    const int warp  = threadIdx.x >> 5;
    const int lane  = threadIdx.x & 31;

    const float* __restrict__ xb = x + (size_t)b * NN * CC;

    // ---------------- Phase 1: gather + max-relative, 8 nodes per warp ----
    for (int i = 0; i < NPW; ++i) {
        const int nl = warp * NPW + i;
        const int n  = tile0 + nl;
        if (n >= NN) {
            ((float4*)feat_s[nl])[lane]      = make_float4(0.f, 0.f, 0.f, 0.f);
            ((float4*)feat_s[nl])[32 + lane] = make_float4(0.f, 0.f, 0.f, 0.f);
            continue;
        }
        // lanes 0..15 hold edge[0][...k] (j), lanes 16..31 hold edge[1][...k] (i)
        const int s = lane >> 4;
        const int k = lane & 15;
        const int idx = __ldg(&edge[(((size_t)s * BB + b) * NN + n) * KK + k]);

        const float4 xs = __ldg((const float4*)(xb + (size_t)n * CC) + lane);

        float4 rel = make_float4(-3.402823466e38f, -3.402823466e38f,
                                 -3.402823466e38f, -3.402823466e38f);
        #pragma unroll 8
        for (int kk = 0; kk < KK; ++kk) {
            const int jn = __shfl_sync(0xffffffffu, idx, kk);        // edge[0]
            const int im = __shfl_sync(0xffffffffu, idx, kk + 16);   // edge[1]
            const float4 vj = __ldg((const float4*)(xb + (size_t)jn * CC) + lane);
            const float4 vi = __ldg((const float4*)(xb + (size_t)im * CC) + lane);
            rel.x = fmaxf(rel.x, vj.x - vi.x);
            rel.y = fmaxf(rel.y, vj.y - vi.y);
            rel.z = fmaxf(rel.z, vj.z - vi.z);
            rel.w = fmaxf(rel.w, vj.w - vi.w);
        }
        ((float4*)feat_s[nl])[lane]      = xs;   // channels 4*lane..4*lane+3
        ((float4*)feat_s[nl])[32 + lane] = rel;  // 128 + 4*lane ..
    }
    __syncwarp();  // warp reads only its own feat rows -> no block sync needed

    // ---------------- Phase 2: per-warp GEMM 8 nodes x 128 outs -----------
    float acc[NPW][4];
    #pragma unroll
    for (int i = 0; i < NPW; ++i)
        #pragma unroll
        for (int j = 0; j < 4; ++j) acc[i][j] = 0.f;

    const float4* __restrict__ Wt4 = (const float4*)g_Wt;
    const int n0 = warp * NPW;

    #pragma unroll 2
    for (int c2 = 0; c2 < C2; ++c2) {
        const float4 wv = __ldg(&Wt4[c2 * 32 + lane]);  // Wt[c2][4*lane..+3], L1-hot
        #pragma unroll
        for (int i = 0; i < NPW; ++i) {
            const float f = feat_s[n0 + i][c2];         // warp-broadcast LDS
            acc[i][0] += f * wv.x;
            acc[i][1] += f * wv.y;
            acc[i][2] += f * wv.z;
            acc[i][3] += f * wv.w;
        }
    }

    const float4 bv = __ldg((const float4*)bias + lane);
    #pragma unroll
    for (int i = 0; i < NPW; ++i) {
        const int n = tile0 + n0 + i;
        if (n < NN) {
            float4 o4;
            o4.x = fmaxf(acc[i][0] + bv.x, 0.f);
            o4.y = fmaxf(acc[i][1] + bv.y, 0.f);
            o4.z = fmaxf(acc[i][2] + bv.z, 0.f);
            o4.w = fmaxf(acc[i][3] + bv.w, 0.f);
            ((float4*)(out + ((size_t)b * NN + n) * OC))[lane] = o4;
        }
    }
}

extern "C" void kernel_launch(void* const* d_in, const int* in_sizes, int n_in,
                              void* d_out, int out_size) {
    const float* x    = (const float*)d_in[0];  // [4,10000,128] f32
    const int*   edge = (const int*)  d_in[1];  // [2,4,10000,16] i32
    const float* W    = (const float*)d_in[2];  // [128,256] f32
    const float* bias = (const float*)d_in[3];  // [128] f32
    float* out = (float*)d_out;                 // [4,10000,128] f32

    transpose_W_kernel<<<(C2 * OC + 255) / 256, 256>>>(W);

    dim3 grid((NN + TILE - 1) / TILE, BB);
    mrconv_kernel<<<grid, NTHREADS>>>(x, edge, bias, out);
}

// round 3
// speedup vs baseline: 1.8263x; 1.5236x over previous
#include <cuda_runtime.h>
#include <cuda_bf16.h>

#define BB 4
#define NN 10000
#define CC 128
#define KK 16
#define OC 128
#define C2 256        // 2*C
#define TILE 64       // nodes per CTA
#define NPW 8         // nodes per warp (phase 1)
#define NTHREADS 256  // 8 warps
#define PITCH 264     // bf16 elems per feat row (256 + 8 pad -> conflict-free LDSM)

// Arranged weight fragments for mma.m16n8k16 (B col-major fragment layout):
// g_Wb[ktile][ntile][lane] = uint4{ hi_b0, hi_b1, lo_b0, lo_b1 }
//   b0 = bf16x2( Wd[k0+(lane%4)*2][n], Wd[k0+(lane%4)*2+1][n] )
//   b1 = same with k0+8,  n = ntile*8 + lane/4
// where Wd[c2][o]: c2<128 -> W[o][2*c2] (self), c2>=128 -> W[o][2*(c2-128)+1] (rel)
__device__ uint4 g_Wb[16 * 16 * 32];

__device__ __forceinline__ unsigned pack_bf16(float a, float b) {
    __nv_bfloat162 h = __floats2bfloat162_rn(a, b);
    return *reinterpret_cast<unsigned*>(&h);
}

__global__ void arrange_W_kernel(const float* __restrict__ W) {
    int tid = blockIdx.x * blockDim.x + threadIdx.x;   // 8192 threads
    if (tid >= 16 * 16 * 32) return;
    int lane  = tid & 31;
    int ntile = (tid >> 5) & 15;
    int ktile = tid >> 9;

    int n  = ntile * 8 + (lane >> 2);
    int k0 = ktile * 16 + (lane & 3) * 2;

    float wv[4], hi[4], lo[4];
    int kk[4] = {k0, k0 + 1, k0 + 8, k0 + 9};
    #pragma unroll
    for (int i = 0; i < 4; ++i) {
        int c2 = kk[i];
        int src_c = (c2 < CC) ? (2 * c2) : (2 * (c2 - CC) + 1);
        wv[i] = W[n * C2 + src_c];
        hi[i] = __bfloat162float(__float2bfloat16(wv[i]));
        lo[i] = wv[i] - hi[i];
    }
    uint4 r;
    r.x = pack_bf16(hi[0], hi[1]);
    r.y = pack_bf16(hi[2], hi[3]);
    r.z = pack_bf16(lo[0], lo[1]);
    r.w = pack_bf16(lo[2], lo[3]);
    g_Wb[tid] = r;
}

__device__ __forceinline__ void mma_bf16(float* d, unsigned a0, unsigned a1,
                                         unsigned a2, unsigned a3,
                                         unsigned b0, unsigned b1) {
    asm volatile(
        "mma.sync.aligned.m16n8k16.row.col.f32.bf16.bf16.f32 "
        "{%0,%1,%2,%3}, {%4,%5,%6,%7}, {%8,%9}, {%0,%1,%2,%3};"
        : "+f"(d[0]), "+f"(d[1]), "+f"(d[2]), "+f"(d[3])
        : "r"(a0), "r"(a1), "r"(a2), "r"(a3), "r"(b0), "r"(b1));
}

__device__ __forceinline__ void ldsm_x4(unsigned& r0, unsigned& r1,
                                        unsigned& r2, unsigned& r3, unsigned addr) {
    asm volatile("ldmatrix.sync.aligned.m8n8.x4.shared.b16 {%0,%1,%2,%3}, [%4];"
                 : "=r"(r0), "=r"(r1), "=r"(r2), "=r"(r3) : "r"(addr));
}

__global__ void __launch_bounds__(NTHREADS, 3)
mrconv_kernel(const float* __restrict__ x,
              const int*   __restrict__ edge,
              const float* __restrict__ bias,
              float*       __restrict__ out) {
    __shared__ __nv_bfloat16 feat_hi[TILE][PITCH];
    __shared__ __nv_bfloat16 feat_lo[TILE][PITCH];

    const int b     = blockIdx.y;
    const int tile0 = blockIdx.x * TILE;
    const int warp  = threadIdx.x >> 5;
    const int lane  = threadIdx.x & 31;

    const float* __restrict__ xb = x + (size_t)b * NN * CC;

    // ---------------- Phase 1: gather + max-relative, 8 nodes per warp ----
    for (int i = 0; i < NPW; ++i) {
        const int nl = warp * NPW + i;
        const int n  = tile0 + nl;
        uint2* hs  = (uint2*)&feat_hi[nl][4 * lane];          // self channels
        uint2* hr  = (uint2*)&feat_hi[nl][CC + 4 * lane];     // rel channels
        uint2* ls  = (uint2*)&feat_lo[nl][4 * lane];
        uint2* lr  = (uint2*)&feat_lo[nl][CC + 4 * lane];
        if (n >= NN) {
            uint2 z = make_uint2(0u, 0u);
            *hs = z; *hr = z; *ls = z; *lr = z;
            continue;
        }
        // lanes 0..15 hold edge[0][...k] (j), lanes 16..31 hold edge[1][...k] (i)
        const int s = lane >> 4;
        const int k = lane & 15;
        const int idx = __ldg(&edge[(((size_t)s * BB + b) * NN + n) * KK + k]);

        const float4 xs = __ldg((const float4*)(xb + (size_t)n * CC) + lane);

        float4 rel = make_float4(-3.402823466e38f, -3.402823466e38f,
                                 -3.402823466e38f, -3.402823466e38f);
        #pragma unroll 8
        for (int kk = 0; kk < KK; ++kk) {
            const int jn = __shfl_sync(0xffffffffu, idx, kk);        // edge[0]
            const int im = __shfl_sync(0xffffffffu, idx, kk + 16);   // edge[1]
            const float4 vj = __ldg((const float4*)(xb + (size_t)jn * CC) + lane);
            const float4 vi = __ldg((const float4*)(xb + (size_t)im * CC) + lane);
            rel.x = fmaxf(rel.x, vj.x - vi.x);
            rel.y = fmaxf(rel.y, vj.y - vi.y);
            rel.z = fmaxf(rel.z, vj.z - vi.z);
            rel.w = fmaxf(rel.w, vj.w - vi.w);
        }
        // split each fp32 into bf16 hi + lo and store
        float xh0 = __bfloat162float(__float2bfloat16(xs.x));
        float xh1 = __bfloat162float(__float2bfloat16(xs.y));
        float xh2 = __bfloat162float(__float2bfloat16(xs.z));
        float xh3 = __bfloat162float(__float2bfloat16(xs.w));
        *hs = make_uint2(pack_bf16(xh0, xh1), pack_bf16(xh2, xh3));
        *ls = make_uint2(pack_bf16(xs.x - xh0, xs.y - xh1),
                         pack_bf16(xs.z - xh2, xs.w - xh3));
        float rh0 = __bfloat162float(__float2bfloat16(rel.x));
        float rh1 = __bfloat162float(__float2bfloat16(rel.y));
        float rh2 = __bfloat162float(__float2bfloat16(rel.z));
        float rh3 = __bfloat162float(__float2bfloat16(rel.w));
        *hr = make_uint2(pack_bf16(rh0, rh1), pack_bf16(rh2, rh3));
        *lr = make_uint2(pack_bf16(rel.x - rh0, rel.y - rh1),
                         pack_bf16(rel.z - rh2, rel.w - rh3));
    }
    __syncthreads();

    // ---------------- Phase 2: tensor-core GEMM ---------------------------
    // warp -> M-tile (16 nodes) x 64 output cols (8 n-tiles of 8)
    const int mtile = warp & 3;           // 0..3 -> nodes mtile*16..+15
    const int nhalf = warp >> 2;          // 0..1 -> out cols nhalf*64..+63

    float acc[8][4];
    #pragma unroll
    for (int t = 0; t < 8; ++t)
        #pragma unroll
        for (int j = 0; j < 4; ++j) acc[t][j] = 0.f;

    // ldmatrix source row/col for this lane
    const int rowA = mtile * 16 + ((lane >> 3) & 1) * 8 + (lane & 7);
    const int kofs = (lane >= 16) ? 8 : 0;
    unsigned aHi = (unsigned)__cvta_generic_to_shared(&feat_hi[rowA][kofs]);
    unsigned aLo = (unsigned)__cvta_generic_to_shared(&feat_lo[rowA][kofs]);

    const uint4* __restrict__ Wb = g_Wb;

    #pragma unroll 4
    for (int kt = 0; kt < 16; ++kt) {
        unsigned h0, h1, h2, h3, l0, l1, l2, l3;
        ldsm_x4(h0, h1, h2, h3, aHi + kt * 32);   // 16 bf16 * 2B per kt
        ldsm_x4(l0, l1, l2, l3, aLo + kt * 32);
        #pragma unroll
        for (int nt = 0; nt < 8; ++nt) {
            const uint4 wb = __ldg(&Wb[((kt * 16) + (nhalf * 8 + nt)) * 32 + lane]);
            mma_bf16(acc[nt], h0, h1, h2, h3, wb.x, wb.y);  // hi*hi
            mma_bf16(acc[nt], h0, h1, h2, h3, wb.z, wb.w);  // hi*lo
            mma_bf16(acc[nt], l0, l1, l2, l3, wb.x, wb.y);  // lo*hi
        }
    }

    // ---------------- Epilogue: bias + relu + store -----------------------
    const int grp = lane >> 2;            // row within 8
    const int cid = (lane & 3) * 2;       // col pair base
    #pragma unroll
    for (int nt = 0; nt < 8; ++nt) {
        const int ncol = nhalf * 64 + nt * 8 + cid;
        const float2 bv = __ldg((const float2*)(bias + ncol));
        #pragma unroll
        for (int half = 0; half < 2; ++half) {
            const int n = tile0 + mtile * 16 + grp + half * 8;
            if (n < NN) {
                float2 o2;
                o2.x = fmaxf(acc[nt][2 * half + 0] + bv.x, 0.f);
                o2.y = fmaxf(acc[nt][2 * half + 1] + bv.y, 0.f);
                *(float2*)(out + ((size_t)b * NN + n) * OC + ncol) = o2;
            }
        }
    }
}

extern "C" void kernel_launch(void* const* d_in, const int* in_sizes, int n_in,
                              void* d_out, int out_size) {
    const float* x    = (const float*)d_in[0];  // [4,10000,128] f32
    const int*   edge = (const int*)  d_in[1];  // [2,4,10000,16] i32
    const float* W    = (const float*)d_in[2];  // [128,256] f32
    const float* bias = (const float*)d_in[3];  // [128] f32
    float* out = (float*)d_out;                 // [4,10000,128] f32

    arrange_W_kernel<<<32, 256>>>(W);

    dim3 grid((NN + TILE - 1) / TILE, BB);
    mrconv_kernel<<<grid, NTHREADS>>>(x, edge, bias, out);
}

// round 4
// speedup vs baseline: 1.8318x; 1.0030x over previous
#include <cuda_runtime.h>
#include <cuda_bf16.h>

#define BB 4
#define NN 10000
#define CC 128
#define KK 16
#define OC 128
#define C2 256        // 2*C
#define TILE 64       // nodes per CTA
#define NPW 8         // nodes per warp (phase 1)
#define NTHREADS 256  // 8 warps
#define PITCH 264     // bf16 elems per feat row (256 + 8 pad -> conflict-free LDSM)

// Arranged weight fragments for mma.m16n8k16 (B col-major fragment layout):
// g_Wb[ktile][ntile][lane] = uint4{ hi_b0, hi_b1, lo_b0, lo_b1 }
//   b0 = bf16x2( Wd[k0+(lane%4)*2][n], Wd[k0+(lane%4)*2+1][n] )
//   b1 = same with k0+8,  n = ntile*8 + lane/4
// where Wd[c2][o]: c2<128 -> W[o][2*c2] (self), c2>=128 -> W[o][2*(c2-128)+1] (rel)
__device__ uint4 g_Wb[16 * 16 * 32];

__device__ __forceinline__ unsigned pack_bf16(float a, float b) {
    __nv_bfloat162 h = __floats2bfloat162_rn(a, b);
    return *reinterpret_cast<unsigned*>(&h);
}

__global__ void arrange_W_kernel(const float* __restrict__ W) {
    int tid = blockIdx.x * blockDim.x + threadIdx.x;   // 8192 threads
    if (tid >= 16 * 16 * 32) return;
    int lane  = tid & 31;
    int ntile = (tid >> 5) & 15;
    int ktile = tid >> 9;

    int n  = ntile * 8 + (lane >> 2);
    int k0 = ktile * 16 + (lane & 3) * 2;

    float wv[4], hi[4], lo[4];
    int kk[4] = {k0, k0 + 1, k0 + 8, k0 + 9};
    #pragma unroll
    for (int i = 0; i < 4; ++i) {
        int c2 = kk[i];
        int src_c = (c2 < CC) ? (2 * c2) : (2 * (c2 - CC) + 1);
        wv[i] = W[n * C2 + src_c];
        hi[i] = __bfloat162float(__float2bfloat16(wv[i]));
        lo[i] = wv[i] - hi[i];
    }
    uint4 r;
    r.x = pack_bf16(hi[0], hi[1]);
    r.y = pack_bf16(hi[2], hi[3]);
    r.z = pack_bf16(lo[0], lo[1]);
    r.w = pack_bf16(lo[2], lo[3]);
    g_Wb[tid] = r;
}

__device__ __forceinline__ void mma_bf16(float* d, unsigned a0, unsigned a1,
                                         unsigned a2, unsigned a3,
                                         unsigned b0, unsigned b1) {
    asm volatile(
        "mma.sync.aligned.m16n8k16.row.col.f32.bf16.bf16.f32 "
        "{%0,%1,%2,%3}, {%4,%5,%6,%7}, {%8,%9}, {%0,%1,%2,%3};"
        : "+f"(d[0]), "+f"(d[1]), "+f"(d[2]), "+f"(d[3])
        : "r"(a0), "r"(a1), "r"(a2), "r"(a3), "r"(b0), "r"(b1));
}

__device__ __forceinline__ void ldsm_x4(unsigned& r0, unsigned& r1,
                                        unsigned& r2, unsigned& r3, unsigned addr) {
    asm volatile("ldmatrix.sync.aligned.m8n8.x4.shared.b16 {%0,%1,%2,%3}, [%4];"
                 : "=r"(r0), "=r"(r1), "=r"(r2), "=r"(r3) : "r"(addr));
}

__global__ void __launch_bounds__(NTHREADS, 3)
mrconv_kernel(const float* __restrict__ x,
              const int*   __restrict__ edge,
              const float* __restrict__ bias,
              float*       __restrict__ out) {
    __shared__ __nv_bfloat16 feat_hi[TILE][PITCH];
    __shared__ __nv_bfloat16 feat_lo[TILE][PITCH];

    const int b     = blockIdx.y;
    const int tile0 = blockIdx.x * TILE;
    const int warp  = threadIdx.x >> 5;
    const int lane  = threadIdx.x & 31;

    const float* __restrict__ xb = x + (size_t)b * NN * CC;

    // ---------------- Phase 1: gather + max-relative, 8 nodes per warp ----
    for (int i = 0; i < NPW; ++i) {
        const int nl = warp * NPW + i;
        const int n  = tile0 + nl;
        uint2* hs  = (uint2*)&feat_hi[nl][4 * lane];          // self channels
        uint2* hr  = (uint2*)&feat_hi[nl][CC + 4 * lane];     // rel channels
        uint2* ls  = (uint2*)&feat_lo[nl][4 * lane];
        uint2* lr  = (uint2*)&feat_lo[nl][CC + 4 * lane];
        if (n >= NN) {
            uint2 z = make_uint2(0u, 0u);
            *hs = z; *hr = z; *ls = z; *lr = z;
            continue;
        }
        // lanes 0..15 hold edge[0][...k] (j), lanes 16..31 hold edge[1][...k] (i)
        const int s = lane >> 4;
        const int k = lane & 15;
        const int idx = __ldg(&edge[(((size_t)s * BB + b) * NN + n) * KK + k]);

        const float4 xs = __ldg((const float4*)(xb + (size_t)n * CC) + lane);

        float4 rel = make_float4(-3.402823466e38f, -3.402823466e38f,
                                 -3.402823466e38f, -3.402823466e38f);
        #pragma unroll 8
        for (int kk = 0; kk < KK; ++kk) {
            const int jn = __shfl_sync(0xffffffffu, idx, kk);        // edge[0]
            const int im = __shfl_sync(0xffffffffu, idx, kk + 16);   // edge[1]
            const float4 vj = __ldg((const float4*)(xb + (size_t)jn * CC) + lane);
            const float4 vi = __ldg((const float4*)(xb + (size_t)im * CC) + lane);
            rel.x = fmaxf(rel.x, vj.x - vi.x);
            rel.y = fmaxf(rel.y, vj.y - vi.y);
            rel.z = fmaxf(rel.z, vj.z - vi.z);
            rel.w = fmaxf(rel.w, vj.w - vi.w);
        }
        // split each fp32 into bf16 hi + lo and store
        float xh0 = __bfloat162float(__float2bfloat16(xs.x));
        float xh1 = __bfloat162float(__float2bfloat16(xs.y));
        float xh2 = __bfloat162float(__float2bfloat16(xs.z));
        float xh3 = __bfloat162float(__float2bfloat16(xs.w));
        *hs = make_uint2(pack_bf16(xh0, xh1), pack_bf16(xh2, xh3));
        *ls = make_uint2(pack_bf16(xs.x - xh0, xs.y - xh1),
                         pack_bf16(xs.z - xh2, xs.w - xh3));
        float rh0 = __bfloat162float(__float2bfloat16(rel.x));
        float rh1 = __bfloat162float(__float2bfloat16(rel.y));
        float rh2 = __bfloat162float(__float2bfloat16(rel.z));
        float rh3 = __bfloat162float(__float2bfloat16(rel.w));
        *hr = make_uint2(pack_bf16(rh0, rh1), pack_bf16(rh2, rh3));
        *lr = make_uint2(pack_bf16(rel.x - rh0, rel.y - rh1),
                         pack_bf16(rel.z - rh2, rel.w - rh3));
    }
    __syncthreads();

    // ---------------- Phase 2: tensor-core GEMM ---------------------------
    // warp -> M-tile (16 nodes) x 64 output cols (8 n-tiles of 8)
    const int mtile = warp & 3;           // 0..3 -> nodes mtile*16..+15
    const int nhalf = warp >> 2;          // 0..1 -> out cols nhalf*64..+63

    float acc[8][4];
    #pragma unroll
    for (int t = 0; t < 8; ++t)
        #pragma unroll
        for (int j = 0; j < 4; ++j) acc[t][j] = 0.f;

    // ldmatrix source row/col for this lane
    const int rowA = mtile * 16 + ((lane >> 3) & 1) * 8 + (lane & 7);
    const int kofs = (lane >= 16) ? 8 : 0;
    unsigned aHi = (unsigned)__cvta_generic_to_shared(&feat_hi[rowA][kofs]);
    unsigned aLo = (unsigned)__cvta_generic_to_shared(&feat_lo[rowA][kofs]);

    const uint4* __restrict__ Wb = g_Wb;

    #pragma unroll 4
    for (int kt = 0; kt < 16; ++kt) {
        unsigned h0, h1, h2, h3, l0, l1, l2, l3;
        ldsm_x4(h0, h1, h2, h3, aHi + kt * 32);   // 16 bf16 * 2B per kt
        ldsm_x4(l0, l1, l2, l3, aLo + kt * 32);
        #pragma unroll
        for (int nt = 0; nt < 8; ++nt) {
            const uint4 wb = __ldg(&Wb[((kt * 16) + (nhalf * 8 + nt)) * 32 + lane]);
            mma_bf16(acc[nt], h0, h1, h2, h3, wb.x, wb.y);  // hi*hi
            mma_bf16(acc[nt], h0, h1, h2, h3, wb.z, wb.w);  // hi*lo
            mma_bf16(acc[nt], l0, l1, l2, l3, wb.x, wb.y);  // lo*hi
        }
    }

    // ---------------- Epilogue: bias + relu + store -----------------------
    const int grp = lane >> 2;            // row within 8
    const int cid = (lane & 3) * 2;       // col pair base
    #pragma unroll
    for (int nt = 0; nt < 8; ++nt) {
        const int ncol = nhalf * 64 + nt * 8 + cid;
        const float2 bv = __ldg((const float2*)(bias + ncol));
        #pragma unroll
        for (int half = 0; half < 2; ++half) {
            const int n = tile0 + mtile * 16 + grp + half * 8;
            if (n < NN) {
                float2 o2;
                o2.x = fmaxf(acc[nt][2 * half + 0] + bv.x, 0.f);
                o2.y = fmaxf(acc[nt][2 * half + 1] + bv.y, 0.f);
                *(float2*)(out + ((size_t)b * NN + n) * OC + ncol) = o2;
            }
        }
    }
}

extern "C" void kernel_launch(void* const* d_in, const int* in_sizes, int n_in,
                              void* d_out, int out_size) {
    const float* x    = (const float*)d_in[0];  // [4,10000,128] f32
    const int*   edge = (const int*)  d_in[1];  // [2,4,10000,16] i32
    const float* W    = (const float*)d_in[2];  // [128,256] f32
    const float* bias = (const float*)d_in[3];  // [128] f32
    float* out = (float*)d_out;                 // [4,10000,128] f32

    arrange_W_kernel<<<32, 256>>>(W);

    dim3 grid((NN + TILE - 1) / TILE, BB);
    mrconv_kernel<<<grid, NTHREADS>>>(x, edge, bias, out);
}